// round 15
// baseline (speedup 1.0000x reference)
#include <cuda_runtime.h>

#define NBATCH 16384
#define NN 10
#define NPAIR (NN * NN)
#define BPB 8                        // batches per block
#define ROWS (BPB * NN)              // 80 rows per block
#define NTHREADS (2 * ROWS)          // 160 threads: 2 lanes per row
#define VSTRIDE 12                   // padded per-batch v stride (float4 alignment)
#define VROWB (BPB * VSTRIDE * 4)    // bytes per c-row of vs = 384

typedef unsigned long long ull;

__device__ __forceinline__ ull pack2(float a, float b) {
    ull p;
    asm("mov.b64 %0, {%1, %2};" : "=l"(p)
        : "r"(__float_as_uint(a)), "r"(__float_as_uint(b)));
    return p;
}
__device__ __forceinline__ ull add2(ull a, ull b) {
    ull r; asm("add.rn.f32x2 %0, %1, %2;" : "=l"(r) : "l"(a), "l"(b)); return r;
}
__device__ __forceinline__ ull fma2r(ull a, ull b, ull c) {
    ull r; asm("fma.rn.f32x2 %0, %1, %2, %3;" : "=l"(r) : "l"(a), "l"(b), "l"(c)); return r;
}
__device__ __forceinline__ void fma2(ull& acc, ull a, ull b) {
    asm("fma.rn.f32x2 %0, %1, %2, %0;" : "+l"(acc) : "l"(a), "l"(b));
}
__device__ __forceinline__ void unpack2(ull p, float& lo, float& hi) {
    unsigned int a, b;
    asm("mov.b64 {%0, %1}, %2;" : "=r"(a), "=r"(b) : "l"(p));
    lo = __uint_as_float(a); hi = __uint_as_float(b);
}
__device__ __forceinline__ float lrelu(float x) { return fmaxf(x, 0.2f * x); }

__global__ void __launch_bounds__(NTHREADS, 7)
gpn_kernel(const float* __restrict__ pos, const float* __restrict__ ori,
           const float* __restrict__ Wp,  const float* __restrict__ bp,
           const float* __restrict__ W1,  const float* __restrict__ b1,
           const float* __restrict__ W2,  const float* __restrict__ b2,
           const float* __restrict__ W3,  const float* __restrict__ b3,
           float* __restrict__ out, int wadj)
{
    __shared__ float us[32 * ROWS];              // u, [c][row]             10240 B
    __shared__ float vs[32 * BPB * VSTRIDE];     // v, [c][b*12 + j]        12288 B
    __shared__ ull   W2d[32 * 8];                // 0.4*W2 duplicated f32x2  2048 B
    __shared__ ull   b2d[8];
    __shared__ float W3s[16], b3s[2];
    __shared__ float xs0[ROWS], xs1[ROWS], xs2[ROWS];
    __shared__ float wA[96], wB[96], wab[32], wbb[32];

    int t = threadIdx.x;

    // ---- stage: fuse front-end weights in-block ----
    // A = Wp @ W1[:16], Bm = Wp @ W1[16:], ab = bp@W1[:16]+b1, bb = bp@W1[16:]
    if (t < 96) {
        int r = t >> 5, c = t & 31;
        float a = 0.f, bm = 0.f;
#pragma unroll
        for (int m = 0; m < 16; m++) {
            float w = Wp[r * 16 + m];
            a  = fmaf(w, W1[m * 32 + c], a);
            bm = fmaf(w, W1[(16 + m) * 32 + c], bm);
        }
        wA[t] = a; wB[t] = bm;
    } else if (t < 128) {
        int c = t - 96;
        float a = b1[c], bm = 0.f;
#pragma unroll
        for (int m = 0; m < 16; m++) {
            float w = bp[m];
            a  = fmaf(w, W1[m * 32 + c], a);
            bm = fmaf(w, W1[(16 + m) * 32 + c], bm);
        }
        wab[c] = a; wbb[c] = bm;
    }
    if (t < ROWS) {
        int g = blockIdx.x * ROWS + t;
        float2 p = reinterpret_cast<const float2*>(pos)[g];
        xs0[t] = p.x; xs1[t] = p.y; xs2[t] = ori[g];
    }
    // W2 pre-scaled by 0.4: lrelu(t) = 0.4*(1.5t + |t|), the 0.4 folds into W2
    for (int i0 = t; i0 < 256; i0 += NTHREADS) {
        float w = 0.4f * W2[i0];
        W2d[i0] = pack2(w, w);
    }
    if (t < 8)  { float w = b2[t]; b2d[t] = pack2(w, w); }
    if (t < 16) W3s[t] = W3[t];
    if (t < 2)  b3s[t] = b3[t];
    __syncthreads();

    // ---- phase 1: compute u and v, transposed ----
    for (int idx = t; idx < 32 * ROWS; idx += NTHREADS) {
        int c = idx / ROWS, node = idx - c * ROWS;
        float x0 = xs0[node], x1 = xs1[node], x2 = xs2[node];
        int nb = node / NN, ni = node - nb * NN;
        us[c * ROWS + node] =
            fmaf(x0, wA[c], fmaf(x1, wA[32 + c], fmaf(x2, wA[64 + c], wab[c])));
        vs[c * (BPB * VSTRIDE) + nb * VSTRIDE + ni] =
            fmaf(x0, wB[c], fmaf(x1, wB[32 + c], fmaf(x2, wB[64 + c], wbb[c])));
    }
    __syncthreads();

    // ---- phase 2: lanes (2m, 2m+1) co-own row (b, i) ----
    // Lane `half` computes activated groups {2*half, 2*half+1} plus g4; the
    // other two arrive via shfl_xor. Accumulators in LANE-LOCAL group order
    // [own0, own1, recv0, recv1, g4]; epilogue resolves the permutation.
    int row  = t >> 1;            // 0..79
    int half = t & 1;
    int b = row / NN;
    int i = row - b * NN;

    const ull K15 = 0x3FC000003FC00000ULL;  // (1.5f, 1.5f)
    const ull KAB = 0x7FFFFFFF7FFFFFFFULL;  // abs mask

    ull acc[5][4];
#pragma unroll
    for (int g = 0; g < 5; g++)
#pragma unroll
        for (int q = 0; q < 4; q++)
            acc[g][q] = b2d[half * 4 + q];

    const float* usp = us + row;
    const char*  vbase = (const char*)(vs + b * VSTRIDE);
    int voff = half * 16;                    // own v quad: bytes [voff, voff+16)
    const ull* w2p = W2d + half * 4;

    // prefetch c=0
    float un = usp[0];
    ulonglong2 vo = *reinterpret_cast<const ulonglong2*>(vbase + voff);
    ull        v4 = *reinterpret_cast<const ull*>(vbase + 32);

#pragma unroll
    for (int c = 0; c < 32; c++) {
        ull cuu = pack2(un, un);
        ulonglong2 cvo = vo;
        ull cv4 = v4;

        if (c < 31) {
            un = usp[(c + 1) * ROWS];
            const char* nv = vbase + (c + 1) * VROWB;
            vo = *reinterpret_cast<const ulonglong2*>(nv + voff);
            v4 = *reinterpret_cast<const ull*>(nv + 32);
        }

        // own activations: p = 1.5t + |t| ; lrelu(t)*W2 == p*(0.4*W2)
        ull t0 = add2(cuu, cvo.x);
        ull sA = fma2r(t0, K15, t0 & KAB);
        ull t1 = add2(cuu, cvo.y);
        ull sB = fma2r(t1, K15, t1 & KAB);
        ull t4 = add2(cuu, cv4);
        ull s4 = fma2r(t4, K15, t4 & KAB);

        // exchange with partner lane (identical bits to local recompute)
        ull rA = __shfl_xor_sync(0xFFFFFFFF, sA, 1);
        ull rB = __shfl_xor_sync(0xFFFFFFFF, sB, 1);

        const ull* w = w2p + c * 8;
        ulonglong2 cw01 = *reinterpret_cast<const ulonglong2*>(w);
        ulonglong2 cw23 = *reinterpret_cast<const ulonglong2*>(w + 2);

        ull sl[5] = { sA, sB, rA, rB, s4 };
#pragma unroll
        for (int g = 0; g < 5; g++) {
            fma2(acc[g][0], sl[g], cw01.x);
            fma2(acc[g][1], sl[g], cw01.y);
            fma2(acc[g][2], sl[g], cw23.x);
            fma2(acc[g][3], sl[g], cw23.y);
        }
    }

    // ---- epilogue ----
    size_t rowbase = (size_t)(blockIdx.x * BPB + b) * NPAIR + (size_t)i * NN;
    float* edge = out + rowbase * 2;
    float* adj  = out + (size_t)NBATCH * NPAIR * 2 + rowbase;

    const float* w3p = W3s + half * 8;
    float bias0 = (half == 0) ? b3s[0] : 0.f;
    float bias1 = (half == 0) ? b3s[1] : 0.f;

    // partial W3 head per local group (own 4 q's)
    float eA0[5], eA1[5], eB0[5], eB1[5];
#pragma unroll
    for (int lg = 0; lg < 5; lg++) {
        float a0 = bias0, a1 = bias1, c0 = bias0, c1 = bias1;
#pragma unroll
        for (int q = 0; q < 4; q++) {
            float h0, h1;
            unpack2(acc[lg][q], h0, h1);
            h0 = lrelu(h0); h1 = lrelu(h1);
            float w0 = w3p[2 * q], w1 = w3p[2 * q + 1];
            a0 = fmaf(h0, w0, a0); a1 = fmaf(h0, w1, a1);
            c0 = fmaf(h1, w0, c0); c1 = fmaf(h1, w1, c1);
        }
        eA0[lg] = a0; eA1[lg] = a1; eB0[lg] = c0; eB1[lg] = c1;
    }

    // butterfly: partner's partial of the SAME global group lives at partner's
    // local index lg^2 (lg<4) / 4 (lg==4); exchanging eX[lg^2] pairs them.
#pragma unroll
    for (int lg = 0; lg < 5; lg++) {
        int pl = (lg < 4) ? (lg ^ 2) : 4;
        float fA0 = eA0[lg] + __shfl_xor_sync(0xFFFFFFFF, eA0[pl], 1);
        float fA1 = eA1[lg] + __shfl_xor_sync(0xFFFFFFFF, eA1[pl], 1);
        float fB0 = eB0[lg] + __shfl_xor_sync(0xFFFFFFFF, eB0[pl], 1);
        float fB1 = eB1[lg] + __shfl_xor_sync(0xFFFFFFFF, eB1[pl], 1);

        // global group of local lg; lane stores element `half` of it
        int G = (lg < 4) ? (lg ^ (half << 1)) : 4;
        int j = 2 * G + half;
        int sj = (j == i) ? 0 : ((j < i) ? j + 1 : j);
        float2 ev;
        ev.x = half ? fB0 : fA0;
        ev.y = half ? fB1 : fA1;
        reinterpret_cast<float2*>(edge)[sj] = ev;
        if (wadj)
            adj[sj] = (ev.y > ev.x) ? 1.f : 0.f;   // argmax of 2; ties -> 0
    }
}

extern "C" void kernel_launch(void* const* d_in, const int* in_sizes, int n_in,
                              void* d_out, int out_size) {
    const float* pos = (const float*)d_in[0];   // (B, N, 2)
    const float* ori = (const float*)d_in[1];   // (B, N, 1)
    const float* Wp  = (const float*)d_in[2];   // (3, 16)
    const float* bp  = (const float*)d_in[3];   // (16,)
    const float* W1  = (const float*)d_in[4];   // (32, 32)
    const float* b1  = (const float*)d_in[5];   // (32,)
    const float* W2  = (const float*)d_in[6];   // (32, 8)
    const float* b2  = (const float*)d_in[7];   // (8,)
    const float* W3  = (const float*)d_in[8];   // (8, 2)
    const float* b3  = (const float*)d_in[9];   // (2,)
    float* out = (float*)d_out;

    int wadj = (out_size >= NBATCH * NPAIR * 3) ? 1 : 0;

    gpn_kernel<<<NBATCH / BPB, NTHREADS>>>(pos, ori, Wp, bp, W1, b1,
                                           W2, b2, W3, b3, out, wadj);
}

// round 16
// speedup vs baseline: 1.1627x; 1.1627x over previous
#include <cuda_runtime.h>

#define NBATCH 16384
#define NN 10
#define NPAIR (NN * NN)
#define BPB 8                        // batches per block
#define ROWS (BPB * NN)              // 80 rows per block
#define NTHREADS (2 * ROWS)          // 160 threads: 2 lanes per row
#define VSTRIDE 12                   // padded per-batch v stride (float4 alignment)
#define VROWB (BPB * VSTRIDE * 4)    // bytes per c-row of vs = 384

typedef unsigned long long ull;

__device__ __forceinline__ ull pack2(float a, float b) {
    ull p;
    asm("mov.b64 %0, {%1, %2};" : "=l"(p)
        : "r"(__float_as_uint(a)), "r"(__float_as_uint(b)));
    return p;
}
__device__ __forceinline__ ull add2(ull a, ull b) {
    ull r; asm("add.rn.f32x2 %0, %1, %2;" : "=l"(r) : "l"(a), "l"(b)); return r;
}
__device__ __forceinline__ ull fma2r(ull a, ull b, ull c) {
    ull r; asm("fma.rn.f32x2 %0, %1, %2, %3;" : "=l"(r) : "l"(a), "l"(b), "l"(c)); return r;
}
__device__ __forceinline__ void fma2(ull& acc, ull a, ull b) {
    asm("fma.rn.f32x2 %0, %1, %2, %0;" : "+l"(acc) : "l"(a), "l"(b));
}
__device__ __forceinline__ void unpack2(ull p, float& lo, float& hi) {
    unsigned int a, b;
    asm("mov.b64 {%0, %1}, %2;" : "=r"(a), "=r"(b) : "l"(p));
    lo = __uint_as_float(a); hi = __uint_as_float(b);
}
__device__ __forceinline__ float lrelu(float x) { return fmaxf(x, 0.2f * x); }

__global__ void __launch_bounds__(NTHREADS, 6)
gpn_kernel(const float* __restrict__ pos, const float* __restrict__ ori,
           const float* __restrict__ Wp,  const float* __restrict__ bp,
           const float* __restrict__ W1,  const float* __restrict__ b1,
           const float* __restrict__ W2,  const float* __restrict__ b2,
           const float* __restrict__ W3,  const float* __restrict__ b3,
           float* __restrict__ out, int wadj)
{
    __shared__ float us[32 * ROWS];              // u, [c][row]             10240 B
    __shared__ float vs[32 * BPB * VSTRIDE];     // v, [c][b*12 + j]        12288 B
    __shared__ ull   W2d[32 * 8];                // 0.4*W2 duplicated f32x2  2048 B
    __shared__ ull   b2d[8];
    __shared__ float W3s[16], b3s[2];
    __shared__ float xs0[ROWS], xs1[ROWS], xs2[ROWS];
    __shared__ float wA[96], wB[96], wab[32], wbb[32];

    int t = threadIdx.x;

    // ---- stage: fuse front-end weights in-block ----
    // A = Wp @ W1[:16], Bm = Wp @ W1[16:], ab = bp@W1[:16]+b1, bb = bp@W1[16:]
    if (t < 96) {
        int r = t >> 5, c = t & 31;
        float a = 0.f, bm = 0.f;
#pragma unroll
        for (int m = 0; m < 16; m++) {
            float w = Wp[r * 16 + m];
            a  = fmaf(w, W1[m * 32 + c], a);
            bm = fmaf(w, W1[(16 + m) * 32 + c], bm);
        }
        wA[t] = a; wB[t] = bm;
    } else if (t < 128) {
        int c = t - 96;
        float a = b1[c], bm = 0.f;
#pragma unroll
        for (int m = 0; m < 16; m++) {
            float w = bp[m];
            a  = fmaf(w, W1[m * 32 + c], a);
            bm = fmaf(w, W1[(16 + m) * 32 + c], bm);
        }
        wab[c] = a; wbb[c] = bm;
    }
    if (t < ROWS) {
        int g = blockIdx.x * ROWS + t;
        float2 p = reinterpret_cast<const float2*>(pos)[g];
        xs0[t] = p.x; xs1[t] = p.y; xs2[t] = ori[g];
    }
    // W2 pre-scaled by 0.4: lrelu(t) = 0.4*(1.5t + |t|), the 0.4 folds into W2
    for (int i0 = t; i0 < 256; i0 += NTHREADS) {
        float w = 0.4f * W2[i0];
        W2d[i0] = pack2(w, w);
    }
    if (t < 8)  { float w = b2[t]; b2d[t] = pack2(w, w); }
    if (t < 16) W3s[t] = W3[t];
    if (t < 2)  b3s[t] = b3[t];
    __syncthreads();

    // ---- phase 1: compute u and v, transposed ----
    for (int idx = t; idx < 32 * ROWS; idx += NTHREADS) {
        int c = idx / ROWS, node = idx - c * ROWS;
        float x0 = xs0[node], x1 = xs1[node], x2 = xs2[node];
        int nb = node / NN, ni = node - nb * NN;
        us[c * ROWS + node] =
            fmaf(x0, wA[c], fmaf(x1, wA[32 + c], fmaf(x2, wA[64 + c], wab[c])));
        vs[c * (BPB * VSTRIDE) + nb * VSTRIDE + ni] =
            fmaf(x0, wB[c], fmaf(x1, wB[32 + c], fmaf(x2, wB[64 + c], wbb[c])));
    }
    __syncthreads();

    // ---- phase 2: lanes (2m, 2m+1) co-own row (b, i), GROUP-split ----
    // Lane `half` fully owns pair-groups {2h, 2h+1} (all 8 W2 columns) and
    // accumulates the shared group g4 over its own 4-q half. No cross-lane
    // traffic in the mainloop; g4 is completed by an epilogue butterfly.
    // W2 rows are loaded in own-half-first permuted order so all register
    // indices stay compile-time constant; the epilogue W3 dot uses the same
    // permutation via two base pointers.
    int row  = t >> 1;            // 0..79
    int half = t & 1;
    int b = row / NN;
    int i = row - b * NN;

    const ull K15 = 0x3FC000003FC00000ULL;  // (1.5f, 1.5f)
    const ull KAB = 0x7FFFFFFF7FFFFFFFULL;  // abs mask

    const ull* b2own = b2d + 4 * half;       // own q-half of b2
    const ull* b2oth = b2d + 4 * (half ^ 1);

    ull acc0[8], acc1[8], acc4[4];
#pragma unroll
    for (int q = 0; q < 4; q++) {
        acc0[q]     = b2own[q];   // perm slot q   <- global q: 4h+q
        acc0[q + 4] = b2oth[q];   // perm slot 4+q <- global q: 4(1-h)+q
        acc1[q]     = b2own[q];
        acc1[q + 4] = b2oth[q];
        acc4[q]     = b2own[q];
    }

    const float* usp = us + row;
    const char*  vbase = (const char*)(vs + b * VSTRIDE);
    int voff = half * 16;                    // own v quad: bytes [voff, voff+16)
    const ull* w2own = W2d + 4 * half;       // per-c: + c*8
    const ull* w2oth = W2d + 4 * (half ^ 1);

    // prefetch c=0
    float un = usp[0];
    ulonglong2 vo = *reinterpret_cast<const ulonglong2*>(vbase + voff);
    ull        v4 = *reinterpret_cast<const ull*>(vbase + 32);

#pragma unroll
    for (int c = 0; c < 32; c++) {
        ull cuu = pack2(un, un);
        ulonglong2 cvo = vo;
        ull cv4 = v4;

        if (c < 31) {
            un = usp[(c + 1) * ROWS];
            const char* nv = vbase + (c + 1) * VROWB;
            vo = *reinterpret_cast<const ulonglong2*>(nv + voff);
            v4 = *reinterpret_cast<const ull*>(nv + 32);
        }

        // own activations: p = 1.5t + |t| ; lrelu(t)*W2 == p*(0.4*W2)
        ull t0 = add2(cuu, cvo.x);
        ull s0 = fma2r(t0, K15, t0 & KAB);
        ull t1 = add2(cuu, cvo.y);
        ull s1 = fma2r(t1, K15, t1 & KAB);
        ull t4 = add2(cuu, cv4);
        ull s4 = fma2r(t4, K15, t4 & KAB);

        // W2 row, own half first (broadcast loads)
        ulonglong2 wo01 = *reinterpret_cast<const ulonglong2*>(w2own + c * 8);
        ulonglong2 wo23 = *reinterpret_cast<const ulonglong2*>(w2own + c * 8 + 2);
        ulonglong2 wx01 = *reinterpret_cast<const ulonglong2*>(w2oth + c * 8);
        ulonglong2 wx23 = *reinterpret_cast<const ulonglong2*>(w2oth + c * 8 + 2);

        fma2(acc0[0], s0, wo01.x); fma2(acc0[1], s0, wo01.y);
        fma2(acc0[2], s0, wo23.x); fma2(acc0[3], s0, wo23.y);
        fma2(acc0[4], s0, wx01.x); fma2(acc0[5], s0, wx01.y);
        fma2(acc0[6], s0, wx23.x); fma2(acc0[7], s0, wx23.y);

        fma2(acc1[0], s1, wo01.x); fma2(acc1[1], s1, wo01.y);
        fma2(acc1[2], s1, wo23.x); fma2(acc1[3], s1, wo23.y);
        fma2(acc1[4], s1, wx01.x); fma2(acc1[5], s1, wx01.y);
        fma2(acc1[6], s1, wx23.x); fma2(acc1[7], s1, wx23.y);

        fma2(acc4[0], s4, wo01.x); fma2(acc4[1], s4, wo01.y);
        fma2(acc4[2], s4, wo23.x); fma2(acc4[3], s4, wo23.y);
    }

    // ---- epilogue ----
    size_t rowbase = (size_t)(blockIdx.x * BPB + b) * NPAIR + (size_t)i * NN;
    float* edge = out + rowbase * 2;
    float* adj  = out + (size_t)NBATCH * NPAIR * 2 + rowbase;

    const float* w3own = W3s + 8 * half;         // W3 rows for own q-half
    const float* w3oth = W3s + 8 * (half ^ 1);

    // own groups: full W3 head over permuted acc (slot q<4 -> w3own, else w3oth)
#pragma unroll
    for (int g = 0; g < 2; g++) {
        const ull* a = g ? acc1 : acc0;
        float eA0 = b3s[0], eA1 = b3s[1], eB0 = b3s[0], eB1 = b3s[1];
#pragma unroll
        for (int q = 0; q < 8; q++) {
            const float* w3p = (q < 4) ? w3own : w3oth;
            int qq = q & 3;
            float h0, h1;
            unpack2(a[q], h0, h1);
            h0 = lrelu(h0); h1 = lrelu(h1);
            float w0 = w3p[2 * qq], w1 = w3p[2 * qq + 1];
            eA0 = fmaf(h0, w0, eA0); eA1 = fmaf(h0, w1, eA1);
            eB0 = fmaf(h1, w0, eB0); eB1 = fmaf(h1, w1, eB1);
        }
        int G = 2 * half + g;                    // global group
        int j0 = 2 * G, j1 = 2 * G + 1;
        int s0 = (j0 == i) ? 0 : ((j0 < i) ? j0 + 1 : j0);
        int s1 = (j1 == i) ? 0 : ((j1 < i) ? j1 + 1 : j1);
        float2 e0; e0.x = eA0; e0.y = eA1;
        float2 e1; e1.x = eB0; e1.y = eB1;
        reinterpret_cast<float2*>(edge)[s0] = e0;
        reinterpret_cast<float2*>(edge)[s1] = e1;
        if (wadj) {
            adj[s0] = (eA1 > eA0) ? 1.f : 0.f;   // argmax of 2; ties -> 0
            adj[s1] = (eB1 > eB0) ? 1.f : 0.f;
        }
    }

    // g4: partial over own 4 q, butterfly with partner, store pair j = 8+half
    {
        float eA0 = (half == 0) ? b3s[0] : 0.f;
        float eA1 = (half == 0) ? b3s[1] : 0.f;
        float eB0 = eA0, eB1 = eA1;
#pragma unroll
        for (int q = 0; q < 4; q++) {
            float h0, h1;
            unpack2(acc4[q], h0, h1);
            h0 = lrelu(h0); h1 = lrelu(h1);
            float w0 = w3own[2 * q], w1 = w3own[2 * q + 1];
            eA0 = fmaf(h0, w0, eA0); eA1 = fmaf(h0, w1, eA1);
            eB0 = fmaf(h1, w0, eB0); eB1 = fmaf(h1, w1, eB1);
        }
        eA0 += __shfl_xor_sync(0xFFFFFFFF, eA0, 1);
        eA1 += __shfl_xor_sync(0xFFFFFFFF, eA1, 1);
        eB0 += __shfl_xor_sync(0xFFFFFFFF, eB0, 1);
        eB1 += __shfl_xor_sync(0xFFFFFFFF, eB1, 1);

        int j = 8 + half;
        int sj = (j == i) ? 0 : ((j < i) ? j + 1 : j);
        float2 ev;
        ev.x = half ? eB0 : eA0;
        ev.y = half ? eB1 : eA1;
        reinterpret_cast<float2*>(edge)[sj] = ev;
        if (wadj)
            adj[sj] = (ev.y > ev.x) ? 1.f : 0.f;
    }
}

extern "C" void kernel_launch(void* const* d_in, const int* in_sizes, int n_in,
                              void* d_out, int out_size) {
    const float* pos = (const float*)d_in[0];   // (B, N, 2)
    const float* ori = (const float*)d_in[1];   // (B, N, 1)
    const float* Wp  = (const float*)d_in[2];   // (3, 16)
    const float* bp  = (const float*)d_in[3];   // (16,)
    const float* W1  = (const float*)d_in[4];   // (32, 32)
    const float* b1  = (const float*)d_in[5];   // (32,)
    const float* W2  = (const float*)d_in[6];   // (32, 8)
    const float* b2  = (const float*)d_in[7];   // (8,)
    const float* W3  = (const float*)d_in[8];   // (8, 2)
    const float* b3  = (const float*)d_in[9];   // (2,)
    float* out = (float*)d_out;

    int wadj = (out_size >= NBATCH * NPAIR * 3) ? 1 : 0;

    gpn_kernel<<<NBATCH / BPB, NTHREADS>>>(pos, ori, Wp, bp, W1, b1,
                                           W2, b2, W3, b3, out, wadj);
}

// round 17
// speedup vs baseline: 1.6837x; 1.4481x over previous
#include <cuda_runtime.h>

#define NBATCH 16384
#define NN 10
#define NPAIR (NN * NN)
#define BPB 8                        // batches per block
#define ROWS (BPB * NN)              // 80 rows per block
#define NTHREADS (2 * ROWS)          // 160 threads: 2 lanes per row
#define VSTRIDE 12                   // padded per-batch v stride (float4 alignment)
#define VROWB (BPB * VSTRIDE * 4)    // bytes per c-row of vs = 384

typedef unsigned long long ull;

__device__ __forceinline__ ull pack2(float a, float b) {
    ull p;
    asm("mov.b64 %0, {%1, %2};" : "=l"(p)
        : "r"(__float_as_uint(a)), "r"(__float_as_uint(b)));
    return p;
}
__device__ __forceinline__ void fma2(ull& acc, ull a, ull b) {
    asm("fma.rn.f32x2 %0, %1, %2, %0;" : "+l"(acc) : "l"(a), "l"(b));
}
__device__ __forceinline__ void unpack2(ull p, float& lo, float& hi) {
    unsigned int a, b;
    asm("mov.b64 {%0, %1}, %2;" : "=r"(a), "=r"(b) : "l"(p));
    lo = __uint_as_float(a); hi = __uint_as_float(b);
}
__device__ __forceinline__ float lrelu(float x) { return fmaxf(x, 0.2f * x); }
// activation kernel: lrelu(t)/0.4 = 1.5t + |t| (0.4 folded into W2)
__device__ __forceinline__ float actp(float t) {
    float at = __uint_as_float(__float_as_uint(t) & 0x7FFFFFFFu);
    return fmaf(t, 1.5f, at);   // FFMA-imm (rt=1)
}

__global__ void __launch_bounds__(NTHREADS, 6)
gpn_kernel(const float* __restrict__ pos, const float* __restrict__ ori,
           const float* __restrict__ Wp,  const float* __restrict__ bp,
           const float* __restrict__ W1,  const float* __restrict__ b1,
           const float* __restrict__ W2,  const float* __restrict__ b2,
           const float* __restrict__ W3,  const float* __restrict__ b3,
           float* __restrict__ out, int wadj)
{
    __shared__ float us[32 * ROWS];              // u, [c][row]             10240 B
    __shared__ float vs[32 * BPB * VSTRIDE];     // v, [c][b*12 + j]        12288 B
    __shared__ ull   W2q[32 * 4];                // 0.4*W2, q-packed = raw   1024 B
    __shared__ ull   b2q[4];                     // b2 q-packed = raw
    __shared__ float W3s[16], b3s[2];
    __shared__ float wA[96], wB[96], wab[32], wbb[32];

    int t = threadIdx.x;

    // ---- stage: fuse front-end weights in-block ----
    // A = Wp @ W1[:16], Bm = Wp @ W1[16:], ab = bp@W1[:16]+b1, bb = bp@W1[16:]
    if (t < 96) {
        int r = t >> 5, c = t & 31;
        float a = 0.f, bm = 0.f;
#pragma unroll
        for (int m = 0; m < 16; m++) {
            float w = Wp[r * 16 + m];
            a  = fmaf(w, W1[m * 32 + c], a);
            bm = fmaf(w, W1[(16 + m) * 32 + c], bm);
        }
        wA[t] = a; wB[t] = bm;
    } else if (t < 128) {
        int c = t - 96;
        float a = b1[c], bm = 0.f;
#pragma unroll
        for (int m = 0; m < 16; m++) {
            float w = bp[m];
            a  = fmaf(w, W1[m * 32 + c], a);
            bm = fmaf(w, W1[(16 + m) * 32 + c], bm);
        }
        wab[c] = a; wbb[c] = bm;
    }
    // q-packed 0.4*W2 is just the raw row-major layout, scaled
    {
        float* W2qf = (float*)W2q;
        for (int i0 = t; i0 < 256; i0 += NTHREADS) W2qf[i0] = 0.4f * W2[i0];
        float* b2qf = (float*)b2q;
        if (t < 8)  b2qf[t] = b2[t];
        if (t < 16) W3s[t] = W3[t];
        if (t < 2)  b3s[t] = b3[t];
    }
    __syncthreads();

    // ---- phase 1 (division-free): threads t<80 do c=0..15 of node t,
    //      threads t>=80 do c=16..31 of node t-80 ----
    {
        int node = (t < ROWS) ? t : (t - ROWS);
        int c0   = (t < ROWS) ? 0 : 16;
        int g = blockIdx.x * ROWS + node;
        float2 p = reinterpret_cast<const float2*>(pos)[g];
        float x2 = ori[g];
        int nb = node / NN, ni = node - nb * NN;
        int vcol = nb * VSTRIDE + ni;
#pragma unroll
        for (int cc = 0; cc < 16; cc++) {
            int c = c0 + cc;
            us[c * ROWS + node] =
                fmaf(p.x, wA[c], fmaf(p.y, wA[32 + c], fmaf(x2, wA[64 + c], wab[c])));
            vs[c * (BPB * VSTRIDE) + vcol] =
                fmaf(p.x, wB[c], fmaf(p.y, wB[32 + c], fmaf(x2, wB[64 + c], wbb[c])));
        }
    }
    __syncthreads();

    // ---- phase 2: lanes (2m, 2m+1) co-own row (b, i) ----
    // Lane `half` wholly owns pairs j in {4h, 4h+1, 4h+2, 4h+3, 8+h}.
    // Accumulators are q-packed: acc[p][k] = (h_{2k}, h_{2k+1}) for pair p.
    // W2's q-packed form is its raw layout -> 2 uniform LDS.128 per c shared
    // across all 5 pairs. No cross-lane traffic anywhere in the mainloop.
    int row  = t >> 1;            // 0..79
    int half = t & 1;
    int b = row / NN;
    int i = row - b * NN;

    ull acc[5][4];
#pragma unroll
    for (int p = 0; p < 5; p++)
#pragma unroll
        for (int k = 0; k < 4; k++)
            acc[p][k] = b2q[k];

    const float* usp   = us + row;
    const char*  vbase = (const char*)vs + b * (VSTRIDE * 4) + half * 16;
    const char*  vxb   = (const char*)vs + b * (VSTRIDE * 4) + 32 + half * 4;

    // prefetch c=0
    float un  = usp[0];
    float4 vo = *reinterpret_cast<const float4*>(vbase);
    float  vx = *reinterpret_cast<const float*>(vxb);

#pragma unroll
    for (int c = 0; c < 32; c++) {
        float cu = un;
        float4 cv = vo;
        float cvx = vx;

        if (c < 31) {
            un = usp[(c + 1) * ROWS];
            vo = *reinterpret_cast<const float4*>(vbase + (c + 1) * VROWB);
            vx = *reinterpret_cast<const float*>(vxb + (c + 1) * VROWB);
        }

        // uniform W2 row (broadcast)
        ulonglong2 w01 = *reinterpret_cast<const ulonglong2*>(W2q + c * 4);
        ulonglong2 w23 = *reinterpret_cast<const ulonglong2*>(W2q + c * 4 + 2);

        // per-pair scalar activation, dup, 4 packed FMAs
        float s0 = actp(cu + cv.x);
        ull d0 = pack2(s0, s0);
        fma2(acc[0][0], d0, w01.x); fma2(acc[0][1], d0, w01.y);
        fma2(acc[0][2], d0, w23.x); fma2(acc[0][3], d0, w23.y);

        float s1 = actp(cu + cv.y);
        ull d1 = pack2(s1, s1);
        fma2(acc[1][0], d1, w01.x); fma2(acc[1][1], d1, w01.y);
        fma2(acc[1][2], d1, w23.x); fma2(acc[1][3], d1, w23.y);

        float s2 = actp(cu + cv.z);
        ull d2 = pack2(s2, s2);
        fma2(acc[2][0], d2, w01.x); fma2(acc[2][1], d2, w01.y);
        fma2(acc[2][2], d2, w23.x); fma2(acc[2][3], d2, w23.y);

        float s3 = actp(cu + cv.w);
        ull d3 = pack2(s3, s3);
        fma2(acc[3][0], d3, w01.x); fma2(acc[3][1], d3, w01.y);
        fma2(acc[3][2], d3, w23.x); fma2(acc[3][3], d3, w23.y);

        float s4 = actp(cu + cvx);
        ull d4 = pack2(s4, s4);
        fma2(acc[4][0], d4, w01.x); fma2(acc[4][1], d4, w01.y);
        fma2(acc[4][2], d4, w23.x); fma2(acc[4][3], d4, w23.y);
    }

    // ---- epilogue: fully lane-local W3 head + argmax + scatter ----
    size_t rowbase = (size_t)(blockIdx.x * BPB + b) * NPAIR + (size_t)i * NN;
    float* edge = out + rowbase * 2;
    float* adj  = out + (size_t)NBATCH * NPAIR * 2 + rowbase;

#pragma unroll
    for (int p = 0; p < 5; p++) {
        float e0 = b3s[0], e1 = b3s[1];
#pragma unroll
        for (int k = 0; k < 4; k++) {
            float h0, h1;
            unpack2(acc[p][k], h0, h1);     // h_{2k}, h_{2k+1}
            h0 = lrelu(h0); h1 = lrelu(h1);
            e0 = fmaf(h0, W3s[4 * k + 0], e0);
            e1 = fmaf(h0, W3s[4 * k + 1], e1);
            e0 = fmaf(h1, W3s[4 * k + 2], e0);
            e1 = fmaf(h1, W3s[4 * k + 3], e1);
        }
        int j  = (p < 4) ? (4 * half + p) : (8 + half);
        int sj = (j == i) ? 0 : ((j < i) ? j + 1 : j);
        float2 ev; ev.x = e0; ev.y = e1;
        reinterpret_cast<float2*>(edge)[sj] = ev;
        if (wadj)
            adj[sj] = (e1 > e0) ? 1.f : 0.f;   // argmax of 2; ties -> 0
    }
}

extern "C" void kernel_launch(void* const* d_in, const int* in_sizes, int n_in,
                              void* d_out, int out_size) {
    const float* pos = (const float*)d_in[0];   // (B, N, 2)
    const float* ori = (const float*)d_in[1];   // (B, N, 1)
    const float* Wp  = (const float*)d_in[2];   // (3, 16)
    const float* bp  = (const float*)d_in[3];   // (16,)
    const float* W1  = (const float*)d_in[4];   // (32, 32)
    const float* b1  = (const float*)d_in[5];   // (32,)
    const float* W2  = (const float*)d_in[6];   // (32, 8)
    const float* b2  = (const float*)d_in[7];   // (8,)
    const float* W3  = (const float*)d_in[8];   // (8, 2)
    const float* b3  = (const float*)d_in[9];   // (2,)
    float* out = (float*)d_out;

    int wadj = (out_size >= NBATCH * NPAIR * 3) ? 1 : 0;

    gpn_kernel<<<NBATCH / BPB, NTHREADS>>>(pos, ori, Wp, bp, W1, b1,
                                           W2, b2, W3, b3, out, wadj);
}